// round 16
// baseline (speedup 1.0000x reference)
#include <cuda_runtime.h>
#include <cstdint>
#include <cstddef>

#define BB 8
#define NN 16384
#define MM 256
#define CC 128
#define NS 32
#define FPS_T 512
#define CLU 8                 /* cluster size: CTAs per batch */
#define NBUF 8                /* slot ring depth */
#define NSLOT (CLU * 16)      /* 128 warp-keys per buffer */
#define GBLK 296              /* group worker blocks */
#define GT 512                /* group block threads (16 warps) */

/* output layout (concatenated, float32) */
#define GP_OFF 0                      /* grouped_p [8,3,256,32]  */
#define CP_OFF 196608                 /* center_p  [8,256,3]     */
#define FJ_OFF 202752                 /* fj        [8,128,256,32]*/
#define CX_OFF 8591360                /* center_x  [8,128,256,1] */

__device__ int g_cenidx[BB * MM];     /* finalized center indices  */
__device__ int g_done[BB];            /* #finalized centers per b  */

/* ---------- exact-rounding f32x2 helpers (no FMA contraction) ---------- */
__device__ __forceinline__ unsigned long long pk2(float lo, float hi) {
    unsigned long long r;
    asm("mov.b64 %0, {%1,%2};" : "=l"(r) : "f"(lo), "f"(hi));
    return r;
}
__device__ __forceinline__ float2 upk2(unsigned long long v) {
    float2 r;
    asm("mov.b64 {%0,%1}, %2;" : "=f"(r.x), "=f"(r.y) : "l"(v));
    return r;
}
__device__ __forceinline__ unsigned long long add2(unsigned long long a, unsigned long long b) {
    unsigned long long r;
    asm("add.rn.f32x2 %0, %1, %2;" : "=l"(r) : "l"(a), "l"(b));
    return r;
}
__device__ __forceinline__ unsigned long long mul2(unsigned long long a, unsigned long long b) {
    unsigned long long r;
    asm("mul.rn.f32x2 %0, %1, %2;" : "=l"(r) : "l"(a), "l"(b));
    return r;
}
__device__ __forceinline__ uint32_t smem_u32(const void* p) {
    uint32_t a;
    asm("{ .reg .u64 t; cvta.to.shared.u64 t, %1; cvt.u32.u64 %0, t; }"
        : "=r"(a) : "l"(p));
    return a;
}
__device__ __forceinline__ uint32_t mapa_u32(uint32_t local, uint32_t rank) {
    uint32_t r;
    asm("mapa.shared::cluster.u32 %0, %1, %2;" : "=r"(r) : "r"(local), "r"(rank));
    return r;
}
__device__ __forceinline__ void st_relaxed_clu64(uint32_t addr, unsigned long long v) {
    asm volatile("st.relaxed.cluster.shared::cluster.u64 [%0], %1;"
                 :: "r"(addr), "l"(v) : "memory");
}
__device__ __forceinline__ unsigned long long ld_relaxed_clu64(uint32_t addr) {
    unsigned long long v;
    asm volatile("ld.relaxed.cluster.shared::cta.u64 %0, [%1];"
                 : "=l"(v) : "r"(addr) : "memory");
    return v;
}
__device__ __forceinline__ int ld_acquire_gpu(const int* a) {
    int v;
    asm volatile("ld.acquire.gpu.global.b32 %0, [%1];" : "=r"(v) : "l"(a) : "memory");
    return v;
}
__device__ __forceinline__ void st_release_gpu(int* a, int v) {
    asm volatile("st.release.gpu.global.b32 [%0], %1;" :: "l"(a), "r"(v) : "memory");
}

/* =======================================================================
 * Kernel 1: FPS — DIRECT warp-key broadcast: every warp pushes its warp
 * winner key straight to all 8 ranks (no intra-CTA block reduce, no
 * bar.sync 1). Warp0 alone waits for all 128 tagged slots and reduces
 * them (per-lane u64 max of 4, then REDUX high word + masked REDUX low
 * word — exact first-max). One bar.sync(2) per iteration total.
 * Publication of centers by sleeper warp1 of rank0.
 * ===================================================================== */
__global__ void __launch_bounds__(FPS_T, 1) __cluster_dims__(CLU, 1, 1)
fps_kernel(const float* __restrict__ p, float* __restrict__ out)
{
    extern __shared__ float scoord[];                /* sx|sy|sz, 3*NN */
    float* __restrict__ sx = scoord;
    float* __restrict__ sy = scoord + NN;
    float* __restrict__ sz = scoord + 2 * NN;
    __shared__ alignas(8) unsigned long long slots[NBUF][NSLOT];
    __shared__ unsigned swin;

    const int t = threadIdx.x;
    const int r = blockIdx.x & (CLU - 1);
    const int b = blockIdx.x / CLU;
    const int w = t >> 5, lane = t & 31;
    const unsigned g0 = (unsigned)(r * (NN / CLU) + 4 * t);  /* my 4 pts */
    const float* __restrict__ pb = p + (size_t)b * NN * 3;
    float* __restrict__ centerP = out + CP_OFF;

    /* zero the slot ring (tag 0 never matches m=1..255) */
    for (int i = t; i < NBUF * NSLOT; i += FPS_T)
        slots[i >> 7][i & (NSLOT - 1)] = 0ull;

    for (int i = t; i < NN * 3; i += FPS_T) {
        const float v = pb[i];
        const int pt = i / 3, c = i - pt * 3;
        if (c == 0) sx[pt] = v; else if (c == 1) sy[pt] = v; else sz[pt] = v;
    }

    const float4 v0 = *(const float4*)(pb + (size_t)g0 * 3);
    const float4 v1 = *(const float4*)(pb + (size_t)g0 * 3 + 4);
    const float4 v2 = *(const float4*)(pb + (size_t)g0 * 3 + 8);
    unsigned long long X[2], Y[2], Z[2];
    X[0] = pk2(v0.x, v0.w); Y[0] = pk2(v0.y, v1.x); Z[0] = pk2(v0.z, v1.y);
    X[1] = pk2(v1.z, v2.y); Y[1] = pk2(v1.w, v2.z); Z[1] = pk2(v2.x, v2.w);
    float d0 = 1e10f, d1 = 1e10f, d2 = 1e10f, d3 = 1e10f;

    /* remote slot addrs: my warp's slot (r*16+w) at rank=lane (0..7) */
    uint32_t rslot[NBUF];
#pragma unroll
    for (int q = 0; q < NBUF; q++)
        rslot[q] = mapa_u32(smem_u32(&slots[q][r * 16 + w]), (uint32_t)(lane & 7));
    const uint32_t lslot0 = smem_u32(&slots[0][0]);

    float cx = pb[0], cy = pb[1], cz = pb[2];        /* center 0 = point 0 */
    if (r == 0 && w == 1 && lane == 0) {
        centerP[(b * MM + 0) * 3 + 0] = cx;
        centerP[(b * MM + 0) * 3 + 1] = cy;
        centerP[(b * MM + 0) * 3 + 2] = cz;
        g_cenidx[b * MM + 0] = 0;
        st_release_gpu(&g_done[b], 1);
    }

    __syncthreads();   /* SoA cache + slot init complete */
    asm volatile("barrier.cluster.arrive.aligned;" ::: "memory");
    asm volatile("barrier.cluster.wait.aligned;" ::: "memory");

    for (int m = 1; m < MM; m++) {
        const unsigned long long ncx = pk2(-cx, -cx);
        const unsigned long long ncy = pk2(-cy, -cy);
        const unsigned long long ncz = pk2(-cz, -cz);

        /* exact packed distance update: ((dx*dx+dy*dy)+dz*dz), then min */
        {
            unsigned long long dx = add2(X[0], ncx);
            unsigned long long dy = add2(Y[0], ncy);
            unsigned long long dz = add2(Z[0], ncz);
            float2 dv = upk2(add2(add2(mul2(dx, dx), mul2(dy, dy)), mul2(dz, dz)));
            d0 = fminf(d0, dv.x); d1 = fminf(d1, dv.y);
        }
        {
            unsigned long long dx = add2(X[1], ncx);
            unsigned long long dy = add2(Y[1], ncy);
            unsigned long long dz = add2(Z[1], ncz);
            float2 dv = upk2(add2(add2(mul2(dx, dx), mul2(dy, dy)), mul2(dz, dz)));
            d2 = fminf(d2, dv.x); d3 = fminf(d3, dv.y);
        }

        /* local argmax over 4 contiguous (ascending keeps first-max) */
        float bv = d0; unsigned bk = 0;
        if (d1 > bv) { bv = d1; bk = 1; }
        if (d2 > bv) { bv = d2; bk = 2; }
        if (d3 > bv) { bv = d3; bk = 3; }
        const unsigned bi = g0 + bk;

        const int q = m & (NBUF - 1);
        const unsigned tag = (unsigned)m & 0xFFu;

        /* warp argmax: REDUX + ballot + ffs + shfl (key to ALL lanes) */
        const unsigned vb   = __float_as_uint(bv);
        const unsigned wmax = __reduce_max_sync(0xffffffffu, vb);
        const unsigned tied = __ballot_sync(0xffffffffu, vb == wmax);
        const int      src  = __ffs(tied) - 1;
        const unsigned widx_w = __shfl_sync(0xffffffffu, bi, src);
        const unsigned long long key =
            ((unsigned long long)wmax << 32)
            | ((unsigned long long)tag << 14)
            | (unsigned long long)(widx_w ^ 0x3FFFu);

        /* lanes 0..7 of EVERY warp push this warp's key to rank=lane */
        if (lane < CLU)
            st_relaxed_clu64(rslot[q], key);

        unsigned widx;
        if (w != 0) {
            asm volatile("bar.sync 2, 512;" ::: "memory");   /* sleep    */
            widx = swin;
        } else {
            /* warp0 alone: wait for all 128 tagged slots, then reduce */
            const uint32_t base = lslot0 + (uint32_t)((q * NSLOT + lane * 4) * 8);
            unsigned long long a0, a1, a2, a3;
            for (;;) {
                a0 = ld_relaxed_clu64(base);      a1 = ld_relaxed_clu64(base + 8);
                a2 = ld_relaxed_clu64(base + 16); a3 = ld_relaxed_clu64(base + 24);
                const unsigned c0 = ((unsigned)(a0 >> 14) & 0xFFu) ^ tag;
                const unsigned c1 = ((unsigned)(a1 >> 14) & 0xFFu) ^ tag;
                const unsigned c2 = ((unsigned)(a2 >> 14) & 0xFFu) ^ tag;
                const unsigned c3 = ((unsigned)(a3 >> 14) & 0xFFu) ^ tag;
                if (__all_sync(0xffffffffu, (c0 | c1 | c2 | c3) == 0u)) break;
            }
            /* per-lane u64 max of 4 (max val, then min idx) */
            if (a1 > a0) a0 = a1;
            if (a3 > a2) a2 = a3;
            if (a2 > a0) a0 = a2;
            /* cross-lane: REDUX high word, masked REDUX low word */
            const unsigned hi = (unsigned)(a0 >> 32);
            const unsigned vmax = __reduce_max_sync(0xffffffffu, hi);
            const unsigned lo = (hi == vmax) ? (unsigned)a0 : 0u;
            const unsigned lomax = __reduce_max_sync(0xffffffffu, lo);
            widx = (lomax & 0x3FFFu) ^ 0x3FFFu;

            if (lane == 0) swin = widx;
            asm volatile("bar.sync 2, 512;" ::: "memory");   /* release  */
        }

        /* winner coords from SMEM cache (bit-identical to p[widx]) */
        cx = sx[widx]; cy = sy[widx]; cz = sz[widx];

        /* publication by a SLEEPER warp (off the critical chain) */
        if (r == 0 && w == 1 && lane == 0) {
            centerP[(b * MM + m) * 3 + 0] = cx;
            centerP[(b * MM + m) * 3 + 1] = cy;
            centerP[(b * MM + m) * 3 + 2] = cz;
            g_cenidx[b * MM + m] = (int)widx;
            st_release_gpu(&g_done[b], m + 1);   /* publish to workers */
        }
    }

    asm volatile("barrier.cluster.arrive.aligned;" ::: "memory");
    asm volatile("barrier.cluster.wait.aligned;" ::: "memory");
}

/* =======================================================================
 * Kernel 2: group workers (unchanged R15): 512 threads, single-pass
 * 16-slice scan, ordered merge, grouped_p + fj/center_x gathers; runs
 * concurrently with FPS via g_done release/acquire flags.
 * ===================================================================== */
__global__ void __launch_bounds__(GT)
group_kernel(const float* __restrict__ p, const float* __restrict__ x,
             float* __restrict__ out)
{
    __shared__ int swlist[16][NS];
    __shared__ int swcnt[16];
    __shared__ int sidx[NS];

    const int tid = threadIdx.x;
    const int lane = tid & 31;
    const int w = tid >> 5;                    /* 0..15 */
    const float R2 = 0.01f;   /* == f32(0.1*0.1 in double), matches ref */

    for (int tau = blockIdx.x; tau < BB * MM; tau += GBLK) {
        const int m = tau >> 3;
        const int b = tau & 7;
        const int bm = b * MM + m;
        const float* __restrict__ pb = p + (size_t)b * NN * 3;

        /* wait for center m of batch b (single polling thread) */
        if (tid == 0) {
            int backoff = 64;
            while (ld_acquire_gpu(&g_done[b]) < m + 1) {
                __nanosleep(backoff);
                if (backoff < 2048) backoff <<= 1;
            }
        }
        __syncthreads();   /* also fences previous task's smem reuse */

        const int ci = g_cenidx[bm];
        const float cx = __ldg(pb + (size_t)ci * 3 + 0);
        const float cy = __ldg(pb + (size_t)ci * 3 + 1);
        const float cz = __ldg(pb + (size_t)ci * 3 + 2);

        /* single-pass slice scan: warp w covers 1024 points */
        {
            int cnt = 0;
            const int sb = w * (NN / 16), se = sb + (NN / 16);
            for (int base = sb; base < se && cnt < NS; base += 128) {
                unsigned msk[4];
#pragma unroll
                for (int j = 0; j < 4; j++) {
                    const int n = base + j * 32 + lane;
                    const float dx = __fsub_rn(cx, pb[n * 3 + 0]);
                    const float dy = __fsub_rn(cy, pb[n * 3 + 1]);
                    const float dz = __fsub_rn(cz, pb[n * 3 + 2]);
                    const float d2 = __fadd_rn(__fadd_rn(__fmul_rn(dx, dx),
                                                         __fmul_rn(dy, dy)),
                                               __fmul_rn(dz, dz));
                    msk[j] = __ballot_sync(0xffffffffu, d2 < R2);
                }
#pragma unroll
                for (int j = 0; j < 4; j++) {
                    const int n = base + j * 32 + lane;
                    const bool in = (msk[j] >> lane) & 1u;
                    const int pos = cnt + __popc(msk[j] & ((1u << lane) - 1u));
                    if (in && pos < NS) swlist[w][pos] = n;
                    cnt += __popc(msk[j]);
                }
            }
            if (lane == 0) swcnt[w] = (cnt > NS) ? NS : cnt;
        }
        __syncthreads();

        /* merge: prefix over 16 capped counts in slice order, scatter */
        int pfx = 0, total = 0;
#pragma unroll
        for (int j = 0; j < 16; j++) {
            const int cj = swcnt[j];
            if (j < w) pfx += cj;
            total += cj;
        }
        if (total > NS) total = NS;
        if (lane < swcnt[w]) {
            const int pos = pfx + lane;
            if (pos < NS) sidx[pos] = swlist[w][lane];
        }
        __syncthreads();
        if (tid < NS && tid >= total) sidx[tid] = sidx[0];   /* pad */
        __syncthreads();

        /* grouped_p by warp 0 */
        if (w == 0) {
            const int myidx = sidx[lane];
            const float gx = pb[myidx * 3 + 0];
            const float gy = pb[myidx * 3 + 1];
            const float gz = pb[myidx * 3 + 2];
            float* __restrict__ gp = out + GP_OFF;
            gp[((size_t)(b * 3 + 0) * MM + m) * NS + lane] = __fsub_rn(gx, cx);
            gp[((size_t)(b * 3 + 1) * MM + m) * NS + lane] = __fsub_rn(gy, cy);
            gp[((size_t)(b * 3 + 2) * MM + m) * NS + lane] = __fsub_rn(gz, cz);
        }

        /* gathers: 16 channels x 32 samples per round, 8 rounds */
        const int s  = tid & 31;
        const int cl = tid >> 5;                 /* 0..15 */
        const float* __restrict__ xb = x + (size_t)b * CC * NN;
        float* __restrict__ fj = out + FJ_OFF;
        float* __restrict__ cxo = out + CX_OFF;
        const int myn = sidx[s];

#pragma unroll
        for (int rr = 0; rr < 8; rr++) {
            const int c = rr * 16 + cl;
            const float* __restrict__ row = xb + (size_t)c * NN;
            fj[(((size_t)(b * CC + c) * MM + m) << 5) + s] = __ldg(row + myn);
            if (s == 0)
                cxo[(size_t)(b * CC + c) * MM + m] = __ldg(row + ci);
        }
    }
}

/* ======================================================================= */
extern "C" void kernel_launch(void* const* d_in, const int* in_sizes, int n_in,
                              void* d_out, int out_size)
{
    const float* p = (const float*)d_in[0];
    const float* x = (const float*)d_in[1];
    if (n_in >= 2 && in_sizes[0] > in_sizes[1]) {
        p = (const float*)d_in[1];
        x = (const float*)d_in[0];
    }
    float* out = (float*)d_out;

    static cudaStream_t s2 = 0;
    static cudaEvent_t ev0 = 0, ev1 = 0;
    if (!s2) {
        cudaFuncSetAttribute(fps_kernel,
                             cudaFuncAttributeMaxDynamicSharedMemorySize,
                             NN * 3 * (int)sizeof(float));
        cudaStreamCreateWithFlags(&s2, cudaStreamNonBlocking);
        cudaEventCreateWithFlags(&ev0, cudaEventDisableTiming);
        cudaEventCreateWithFlags(&ev1, cudaEventDisableTiming);
    }

    /* fork: group runs concurrently with fps, synced via device flags */
    cudaEventRecord(ev0, 0);
    cudaStreamWaitEvent(s2, ev0, 0);

    fps_kernel<<<BB * CLU, FPS_T, NN * 3 * sizeof(float)>>>(p, out);
    group_kernel<<<GBLK, GT, 0, s2>>>(p, x, out);

    /* join */
    cudaEventRecord(ev1, s2);
    cudaStreamWaitEvent(0, ev1, 0);
}

// round 17
// speedup vs baseline: 1.7452x; 1.7452x over previous
#include <cuda_runtime.h>
#include <cstdint>
#include <cstddef>

#define BB 8
#define NN 16384
#define MM 256
#define CC 128
#define NS 32
#define FPS_T 512
#define CLU 8                 /* cluster size: CTAs per batch */
#define NBUF 8                /* slot ring depth */
#define GBLK 296              /* group worker blocks */
#define GT 512                /* group block threads (16 warps) */

/* output layout (concatenated, float32) */
#define GP_OFF 0                      /* grouped_p [8,3,256,32]  */
#define CP_OFF 196608                 /* center_p  [8,256,3]     */
#define FJ_OFF 202752                 /* fj        [8,128,256,32]*/
#define CX_OFF 8591360                /* center_x  [8,128,256,1] */

__device__ int g_cenidx[BB * MM];     /* finalized center indices  */
__device__ int g_done[BB];            /* #finalized centers per b  */

/* ---------- exact-rounding f32x2 helpers (no FMA contraction) ---------- */
__device__ __forceinline__ unsigned long long pk2(float lo, float hi) {
    unsigned long long r;
    asm("mov.b64 %0, {%1,%2};" : "=l"(r) : "f"(lo), "f"(hi));
    return r;
}
__device__ __forceinline__ float2 upk2(unsigned long long v) {
    float2 r;
    asm("mov.b64 {%0,%1}, %2;" : "=f"(r.x), "=f"(r.y) : "l"(v));
    return r;
}
__device__ __forceinline__ unsigned long long add2(unsigned long long a, unsigned long long b) {
    unsigned long long r;
    asm("add.rn.f32x2 %0, %1, %2;" : "=l"(r) : "l"(a), "l"(b));
    return r;
}
__device__ __forceinline__ unsigned long long mul2(unsigned long long a, unsigned long long b) {
    unsigned long long r;
    asm("mul.rn.f32x2 %0, %1, %2;" : "=l"(r) : "l"(a), "l"(b));
    return r;
}
__device__ __forceinline__ uint32_t smem_u32(const void* p) {
    uint32_t a;
    asm("{ .reg .u64 t; cvta.to.shared.u64 t, %1; cvt.u32.u64 %0, t; }"
        : "=r"(a) : "l"(p));
    return a;
}
__device__ __forceinline__ uint32_t mapa_u32(uint32_t local, uint32_t rank) {
    uint32_t r;
    asm("mapa.shared::cluster.u32 %0, %1, %2;" : "=r"(r) : "r"(local), "r"(rank));
    return r;
}
__device__ __forceinline__ void st_relaxed_clu64(uint32_t addr, unsigned long long v) {
    asm volatile("st.relaxed.cluster.shared::cluster.u64 [%0], %1;"
                 :: "r"(addr), "l"(v) : "memory");
}
__device__ __forceinline__ unsigned long long ld_relaxed_clu64(uint32_t addr) {
    unsigned long long v;
    asm volatile("ld.relaxed.cluster.shared::cta.u64 %0, [%1];"
                 : "=l"(v) : "r"(addr) : "memory");
    return v;
}
__device__ __forceinline__ int ld_acquire_gpu(const int* a) {
    int v;
    asm volatile("ld.acquire.gpu.global.b32 %0, [%1];" : "=r"(v) : "l"(a) : "memory");
    return v;
}
__device__ __forceinline__ void st_release_gpu(int* a, int v) {
    asm volatile("st.release.gpu.global.b32 [%0], %1;" :: "l"(a), "r"(v) : "memory");
}

/* =======================================================================
 * Kernel 1: FPS — R15 structure (single spinner warp0, split barrier,
 * 1 remote store per CTA pair per iter) with a shortened intra-CTA
 * handoff: the winning lane of each warp writes its FULL tagged u64 key
 * to skeys[w] (no shfl, no separate idx array); warp0 reduces via one
 * LDS.64 + REDUX(hi) + masked REDUX(lo) — exact first-max. Publication
 * of centers by sleeper warp1 of rank0.
 * ===================================================================== */
__global__ void __launch_bounds__(FPS_T, 1) __cluster_dims__(CLU, 1, 1)
fps_kernel(const float* __restrict__ p, float* __restrict__ out)
{
    extern __shared__ float scoord[];                /* sx|sy|sz, 3*NN */
    float* __restrict__ sx = scoord;
    float* __restrict__ sy = scoord + NN;
    float* __restrict__ sz = scoord + 2 * NN;
    __shared__ alignas(8) unsigned long long skeys[16];
    __shared__ alignas(8) unsigned long long slots[NBUF][CLU];
    __shared__ unsigned swin;

    const int t = threadIdx.x;
    const int r = blockIdx.x & (CLU - 1);
    const int b = blockIdx.x / CLU;
    const int w = t >> 5, lane = t & 31;
    const unsigned g0 = (unsigned)(r * (NN / CLU) + 4 * t);  /* my 4 pts */
    const float* __restrict__ pb = p + (size_t)b * NN * 3;
    float* __restrict__ centerP = out + CP_OFF;

    if (t < NBUF * CLU) slots[t >> 3][t & 7] = 0ull;

    for (int i = t; i < NN * 3; i += FPS_T) {
        const float v = pb[i];
        const int pt = i / 3, c = i - pt * 3;
        if (c == 0) sx[pt] = v; else if (c == 1) sy[pt] = v; else sz[pt] = v;
    }

    const float4 v0 = *(const float4*)(pb + (size_t)g0 * 3);
    const float4 v1 = *(const float4*)(pb + (size_t)g0 * 3 + 4);
    const float4 v2 = *(const float4*)(pb + (size_t)g0 * 3 + 8);
    unsigned long long X[2], Y[2], Z[2];
    X[0] = pk2(v0.x, v0.w); Y[0] = pk2(v0.y, v1.x); Z[0] = pk2(v0.z, v1.y);
    X[1] = pk2(v1.z, v2.y); Y[1] = pk2(v1.w, v2.z); Z[1] = pk2(v2.x, v2.w);
    float d0 = 1e10f, d1 = 1e10f, d2 = 1e10f, d3 = 1e10f;

    uint32_t rslot[NBUF];
#pragma unroll
    for (int q = 0; q < NBUF; q++)
        rslot[q] = mapa_u32(smem_u32(&slots[q][r]), (uint32_t)(lane & 7));
    const uint32_t lslot0 = smem_u32(&slots[0][0]);

    float cx = pb[0], cy = pb[1], cz = pb[2];        /* center 0 = point 0 */
    if (r == 0 && w == 1 && lane == 0) {
        centerP[(b * MM + 0) * 3 + 0] = cx;
        centerP[(b * MM + 0) * 3 + 1] = cy;
        centerP[(b * MM + 0) * 3 + 2] = cz;
        g_cenidx[b * MM + 0] = 0;
        st_release_gpu(&g_done[b], 1);
    }

    __syncthreads();   /* SoA cache + slot init complete */
    asm volatile("barrier.cluster.arrive.aligned;" ::: "memory");
    asm volatile("barrier.cluster.wait.aligned;" ::: "memory");

    for (int m = 1; m < MM; m++) {
        const unsigned long long ncx = pk2(-cx, -cx);
        const unsigned long long ncy = pk2(-cy, -cy);
        const unsigned long long ncz = pk2(-cz, -cz);

        /* exact packed distance update: ((dx*dx+dy*dy)+dz*dz), then min */
        {
            unsigned long long dx = add2(X[0], ncx);
            unsigned long long dy = add2(Y[0], ncy);
            unsigned long long dz = add2(Z[0], ncz);
            float2 dv = upk2(add2(add2(mul2(dx, dx), mul2(dy, dy)), mul2(dz, dz)));
            d0 = fminf(d0, dv.x); d1 = fminf(d1, dv.y);
        }
        {
            unsigned long long dx = add2(X[1], ncx);
            unsigned long long dy = add2(Y[1], ncy);
            unsigned long long dz = add2(Z[1], ncz);
            float2 dv = upk2(add2(add2(mul2(dx, dx), mul2(dy, dy)), mul2(dz, dz)));
            d2 = fminf(d2, dv.x); d3 = fminf(d3, dv.y);
        }

        /* local argmax over 4 contiguous (ascending keeps first-max) */
        float bv = d0; unsigned bk = 0;
        if (d1 > bv) { bv = d1; bk = 1; }
        if (d2 > bv) { bv = d2; bk = 2; }
        if (d3 > bv) { bv = d3; bk = 3; }
        const unsigned bi = g0 + bk;

        const int q = m & (NBUF - 1);
        const unsigned tag = (unsigned)m & 0xFFu;

        /* warp argmax: REDUX; winning lane writes full tagged u64 key */
        const unsigned vb   = __float_as_uint(bv);
        const unsigned wmax = __reduce_max_sync(0xffffffffu, vb);
        const unsigned tied = __ballot_sync(0xffffffffu, vb == wmax);
        const int      src  = __ffs(tied) - 1;
        if (lane == src)
            skeys[w] = ((unsigned long long)wmax << 32)
                     | ((unsigned long long)tag << 14)
                     | (unsigned long long)(bi ^ 0x3FFFu);

        unsigned widx;
        if (w != 0) {
            asm volatile("bar.arrive 1, 512;" ::: "memory");
            asm volatile("bar.sync 2, 512;" ::: "memory");   /* sleep    */
            widx = swin;
        } else {
            asm volatile("bar.sync 1, 512;" ::: "memory");
            /* block argmax: one LDS.64 + REDUX(hi) + masked REDUX(lo) */
            const unsigned long long kw = skeys[lane & 15];
            const unsigned hi   = (unsigned)(kw >> 32);
            const unsigned vmax = __reduce_max_sync(0xffffffffu, hi);
            const unsigned lo   = (hi == vmax) ? (unsigned)kw : 0u;
            const unsigned lomax = __reduce_max_sync(0xffffffffu, lo);
            const unsigned long long key =
                ((unsigned long long)vmax << 32) | (unsigned long long)lomax;
            if (lane < CLU)            /* 8 lanes push in parallel */
                st_relaxed_clu64(rslot[q], key);

            /* ONLY warp0 spins on the 8 local slots */
            const uint32_t base = lslot0 + (uint32_t)(q * CLU * 8);
            unsigned long long k0, k1, k2, k3, k4, k5, k6, k7;
            for (;;) {
                k0 = ld_relaxed_clu64(base);      k1 = ld_relaxed_clu64(base + 8);
                k2 = ld_relaxed_clu64(base + 16); k3 = ld_relaxed_clu64(base + 24);
                k4 = ld_relaxed_clu64(base + 32); k5 = ld_relaxed_clu64(base + 40);
                k6 = ld_relaxed_clu64(base + 48); k7 = ld_relaxed_clu64(base + 56);
                const unsigned t0 = ((unsigned)(k0 >> 14) & 0xFFu) ^ tag;
                const unsigned t1 = ((unsigned)(k1 >> 14) & 0xFFu) ^ tag;
                const unsigned t2 = ((unsigned)(k2 >> 14) & 0xFFu) ^ tag;
                const unsigned t3 = ((unsigned)(k3 >> 14) & 0xFFu) ^ tag;
                const unsigned t4 = ((unsigned)(k4 >> 14) & 0xFFu) ^ tag;
                const unsigned t5 = ((unsigned)(k5 >> 14) & 0xFFu) ^ tag;
                const unsigned t6 = ((unsigned)(k6 >> 14) & 0xFFu) ^ tag;
                const unsigned t7 = ((unsigned)(k7 >> 14) & 0xFFu) ^ tag;
                if ((t0 | t1 | t2 | t3 | t4 | t5 | t6 | t7) == 0u) break;
            }
            if (k1 > k0) k0 = k1;  if (k3 > k2) k2 = k3;
            if (k5 > k4) k4 = k5;  if (k7 > k6) k6 = k7;
            if (k2 > k0) k0 = k2;  if (k6 > k4) k4 = k6;
            if (k4 > k0) k0 = k4;
            widx = ((unsigned)k0 & 0x3FFFu) ^ 0x3FFFu;

            if (lane == 0) swin = widx;
            asm volatile("bar.sync 2, 512;" ::: "memory");   /* release  */
        }

        /* winner coords from SMEM cache (bit-identical to p[widx]) */
        cx = sx[widx]; cy = sy[widx]; cz = sz[widx];

        /* publication by a SLEEPER warp (off the critical chain) */
        if (r == 0 && w == 1 && lane == 0) {
            centerP[(b * MM + m) * 3 + 0] = cx;
            centerP[(b * MM + m) * 3 + 1] = cy;
            centerP[(b * MM + m) * 3 + 2] = cz;
            g_cenidx[b * MM + m] = (int)widx;
            st_release_gpu(&g_done[b], m + 1);   /* publish to workers */
        }
    }

    asm volatile("barrier.cluster.arrive.aligned;" ::: "memory");
    asm volatile("barrier.cluster.wait.aligned;" ::: "memory");
}

/* =======================================================================
 * Kernel 2: group workers (unchanged R15): 512 threads, single-pass
 * 16-slice scan, ordered merge, grouped_p + fj/center_x gathers; runs
 * concurrently with FPS via g_done release/acquire flags.
 * ===================================================================== */
__global__ void __launch_bounds__(GT)
group_kernel(const float* __restrict__ p, const float* __restrict__ x,
             float* __restrict__ out)
{
    __shared__ int swlist[16][NS];
    __shared__ int swcnt[16];
    __shared__ int sidx[NS];

    const int tid = threadIdx.x;
    const int lane = tid & 31;
    const int w = tid >> 5;                    /* 0..15 */
    const float R2 = 0.01f;   /* == f32(0.1*0.1 in double), matches ref */

    for (int tau = blockIdx.x; tau < BB * MM; tau += GBLK) {
        const int m = tau >> 3;
        const int b = tau & 7;
        const int bm = b * MM + m;
        const float* __restrict__ pb = p + (size_t)b * NN * 3;

        /* wait for center m of batch b (single polling thread) */
        if (tid == 0) {
            int backoff = 64;
            while (ld_acquire_gpu(&g_done[b]) < m + 1) {
                __nanosleep(backoff);
                if (backoff < 2048) backoff <<= 1;
            }
        }
        __syncthreads();   /* also fences previous task's smem reuse */

        const int ci = g_cenidx[bm];
        const float cx = __ldg(pb + (size_t)ci * 3 + 0);
        const float cy = __ldg(pb + (size_t)ci * 3 + 1);
        const float cz = __ldg(pb + (size_t)ci * 3 + 2);

        /* single-pass slice scan: warp w covers 1024 points */
        {
            int cnt = 0;
            const int sb = w * (NN / 16), se = sb + (NN / 16);
            for (int base = sb; base < se && cnt < NS; base += 128) {
                unsigned msk[4];
#pragma unroll
                for (int j = 0; j < 4; j++) {
                    const int n = base + j * 32 + lane;
                    const float dx = __fsub_rn(cx, pb[n * 3 + 0]);
                    const float dy = __fsub_rn(cy, pb[n * 3 + 1]);
                    const float dz = __fsub_rn(cz, pb[n * 3 + 2]);
                    const float d2 = __fadd_rn(__fadd_rn(__fmul_rn(dx, dx),
                                                         __fmul_rn(dy, dy)),
                                               __fmul_rn(dz, dz));
                    msk[j] = __ballot_sync(0xffffffffu, d2 < R2);
                }
#pragma unroll
                for (int j = 0; j < 4; j++) {
                    const int n = base + j * 32 + lane;
                    const bool in = (msk[j] >> lane) & 1u;
                    const int pos = cnt + __popc(msk[j] & ((1u << lane) - 1u));
                    if (in && pos < NS) swlist[w][pos] = n;
                    cnt += __popc(msk[j]);
                }
            }
            if (lane == 0) swcnt[w] = (cnt > NS) ? NS : cnt;
        }
        __syncthreads();

        /* merge: prefix over 16 capped counts in slice order, scatter */
        int pfx = 0, total = 0;
#pragma unroll
        for (int j = 0; j < 16; j++) {
            const int cj = swcnt[j];
            if (j < w) pfx += cj;
            total += cj;
        }
        if (total > NS) total = NS;
        if (lane < swcnt[w]) {
            const int pos = pfx + lane;
            if (pos < NS) sidx[pos] = swlist[w][lane];
        }
        __syncthreads();
        if (tid < NS && tid >= total) sidx[tid] = sidx[0];   /* pad */
        __syncthreads();

        /* grouped_p by warp 0 */
        if (w == 0) {
            const int myidx = sidx[lane];
            const float gx = pb[myidx * 3 + 0];
            const float gy = pb[myidx * 3 + 1];
            const float gz = pb[myidx * 3 + 2];
            float* __restrict__ gp = out + GP_OFF;
            gp[((size_t)(b * 3 + 0) * MM + m) * NS + lane] = __fsub_rn(gx, cx);
            gp[((size_t)(b * 3 + 1) * MM + m) * NS + lane] = __fsub_rn(gy, cy);
            gp[((size_t)(b * 3 + 2) * MM + m) * NS + lane] = __fsub_rn(gz, cz);
        }

        /* gathers: 16 channels x 32 samples per round, 8 rounds */
        const int s  = tid & 31;
        const int cl = tid >> 5;                 /* 0..15 */
        const float* __restrict__ xb = x + (size_t)b * CC * NN;
        float* __restrict__ fj = out + FJ_OFF;
        float* __restrict__ cxo = out + CX_OFF;
        const int myn = sidx[s];

#pragma unroll
        for (int rr = 0; rr < 8; rr++) {
            const int c = rr * 16 + cl;
            const float* __restrict__ row = xb + (size_t)c * NN;
            fj[(((size_t)(b * CC + c) * MM + m) << 5) + s] = __ldg(row + myn);
            if (s == 0)
                cxo[(size_t)(b * CC + c) * MM + m] = __ldg(row + ci);
        }
    }
}

/* ======================================================================= */
extern "C" void kernel_launch(void* const* d_in, const int* in_sizes, int n_in,
                              void* d_out, int out_size)
{
    const float* p = (const float*)d_in[0];
    const float* x = (const float*)d_in[1];
    if (n_in >= 2 && in_sizes[0] > in_sizes[1]) {
        p = (const float*)d_in[1];
        x = (const float*)d_in[0];
    }
    float* out = (float*)d_out;

    static cudaStream_t s2 = 0;
    static cudaEvent_t ev0 = 0, ev1 = 0;
    if (!s2) {
        cudaFuncSetAttribute(fps_kernel,
                             cudaFuncAttributeMaxDynamicSharedMemorySize,
                             NN * 3 * (int)sizeof(float));
        cudaStreamCreateWithFlags(&s2, cudaStreamNonBlocking);
        cudaEventCreateWithFlags(&ev0, cudaEventDisableTiming);
        cudaEventCreateWithFlags(&ev1, cudaEventDisableTiming);
    }

    /* fork: group runs concurrently with fps, synced via device flags */
    cudaEventRecord(ev0, 0);
    cudaStreamWaitEvent(s2, ev0, 0);

    fps_kernel<<<BB * CLU, FPS_T, NN * 3 * sizeof(float)>>>(p, out);
    group_kernel<<<GBLK, GT, 0, s2>>>(p, x, out);

    /* join */
    cudaEventRecord(ev1, s2);
    cudaStreamWaitEvent(0, ev1, 0);
}